// round 16
// baseline (speedup 1.0000x reference)
#include <cuda_runtime.h>
#include <cuda_fp16.h>
#include <cstdint>

#define B_SETS 256
#define S_LEN  1024
#define H_DIM  256
#define M_ROWS (B_SETS * S_LEN)

// ---------------------------------------------------------------------------
// Scratch (__device__ globals; allocation-free rule)
// ---------------------------------------------------------------------------
__device__ __half g_act1[(size_t)M_ROWS * H_DIM];  // 128 MB
__device__ __half g_act2[(size_t)M_ROWS * H_DIM];  // 128 MB (x plane for L0)
__device__ __half g_w0[H_DIM * 128];
__device__ __half g_w1[H_DIM * H_DIM];
__device__ __half g_w2[H_DIM * H_DIM];
__device__ float g_msum[B_SETS * H_DIM];   // column sums; zeroed after every read
__device__ float g_cb[B_SETS * H_DIM];     // per-set bias c[b,h]

// ---------------------------------------------------------------------------
// helpers
// ---------------------------------------------------------------------------
__device__ __forceinline__ uint32_t smem_u32(const void* p) {
    uint32_t a;
    asm("{ .reg .u64 t; cvta.to.shared.u64 t, %1; cvt.u32.u64 %0, t; }" : "=r"(a) : "l"(p));
    return a;
}
#define SW128(o) ((uint32_t)(o) ^ ((((uint32_t)(o)) >> 3) & 0x70u))

__device__ __forceinline__ void ldsm_x4(uint32_t* r, uint32_t addr) {
    asm volatile("ldmatrix.sync.aligned.m8n8.x4.shared.b16 {%0,%1,%2,%3}, [%4];"
                 : "=r"(r[0]), "=r"(r[1]), "=r"(r[2]), "=r"(r[3]) : "r"(addr));
}
__device__ __forceinline__ void mma_fp16(float* d, const uint32_t* a, uint32_t b0, uint32_t b1) {
    asm volatile(
        "mma.sync.aligned.m16n8k16.row.col.f32.f16.f16.f32 "
        "{%0,%1,%2,%3},{%4,%5,%6,%7},{%8,%9},{%0,%1,%2,%3};"
        : "+f"(d[0]), "+f"(d[1]), "+f"(d[2]), "+f"(d[3])
        : "r"(a[0]), "r"(a[1]), "r"(a[2]), "r"(a[3]), "r"(b0), "r"(b1));
}
__device__ __forceinline__ float tanh_fast(float x) {
    float r;
    asm("tanh.approx.f32 %0, %1;" : "=f"(r) : "f"(x));
    return r;
}
__device__ __forceinline__ uint32_t pack2h(float a, float b) {
    __half2 t = __floats2half2_rn(a, b);
    return *reinterpret_cast<uint32_t*>(&t);
}
__device__ __forceinline__ void cpa16(uint32_t dst, const void* src) {
    asm volatile("cp.async.cg.shared.global [%0], [%1], 16;" :: "r"(dst), "l"(src));
}
__device__ __forceinline__ void cpa_commit() {
    asm volatile("cp.async.commit_group;");
}
template<int N>
__device__ __forceinline__ void cpa_wait() {
    asm volatile("cp.async.wait_group %0;" :: "n"(N));
}

// ---------------------------------------------------------------------------
// small kernels
// ---------------------------------------------------------------------------
// all three weight conversions in one launch: blocks [0,256)->W0, [256,512)->W1,
// [512,768)->W2
__global__ void prep_w_all_kernel(const float* __restrict__ W0,
                                  const float* __restrict__ W1,
                                  const float* __restrict__ W2,
                                  __half* __restrict__ w0h,
                                  __half* __restrict__ w1h,
                                  __half* __restrict__ w2h) {
    int blk = blockIdx.x;
    const float* W; __half* O; int ldw, K, n;
    if (blk < 256)      { W = W0; O = w0h; ldw = 256; K = 128; n = blk; }
    else if (blk < 512) { W = W1; O = w1h; ldw = 512; K = 256; n = blk - 256; }
    else                { W = W2; O = w2h; ldw = 512; K = 256; n = blk - 512; }
    for (int k = threadIdx.x; k < K; k += blockDim.x)
        O[n * K + k] = __float2half_rn(W[(size_t)n * ldw + k]);
}

// Fused: x fp32 -> fp16 plane AND per-set column sums.
__global__ void prep_x_mean_kernel(const float* __restrict__ x,
                                   __half* __restrict__ hi,
                                   float* __restrict__ msum) {
    int b = blockIdx.x, cz = blockIdx.y, t = threadIdx.x;
    size_t base = (size_t)b * S_LEN * 128 + (size_t)cz * 128 * 128;
    const float* p = x + base + t;
    __half* o = hi + base + t;
    float s = 0.f;
#pragma unroll 8
    for (int i = 0; i < 128; i++) {
        float f = p[(size_t)i * 128];
        s += f;
        o[(size_t)i * 128] = __float2half_rn(f);
    }
    atomicAdd(msum + b * 128 + t, s);
}

// c[b,h] = bias[h] + (1/S) * sum_k msum[b,k] * W[h, koff+k]; then re-zero msum.
__global__ void cbias_kernel(const float* __restrict__ msum, const float* __restrict__ W,
                             const float* __restrict__ bias, float* __restrict__ c,
                             float* __restrict__ msum_zero,
                             int K, int ldw, int koff) {
    __shared__ float ms[H_DIM];
    int b = blockIdx.x, h = threadIdx.x;
    if (h < K) ms[h] = msum[b * K + h] * (1.0f / S_LEN);
    __syncthreads();
    if (h < K) msum_zero[b * K + h] = 0.f;
    const float* wr = W + (size_t)h * ldw + koff;
    float s = bias[h];
#pragma unroll 8
    for (int k = 0; k < K; k++) s += ms[k] * wr[k];
    c[b * H_DIM + h] = s;
}

__global__ void zero_kernel(float* p, int n) {
    int i = blockIdx.x * 256 + threadIdx.x;
    if (i < n) p[i] = 0.f;
}

// ---------------------------------------------------------------------------
// Fused layer (fp16 HMMA, cp.async 2-stage, SMALL CTA = 4 CTAs/SM):
// CTA (128 threads, 4 warps, warp tile 32x64): Out[128 x 64] =
//   tanh(A[128xK] W[64xK]^T + cbias). K chunk 64 (128B rows, SW128).
// Grid (4, M/128): four independent barrier domains per SM hide each
// other's load-wait phases.
// ---------------------------------------------------------------------------
#define A_PL 0
#define W_PL 16384
#define STAGE_BYTES 24576
#define NSTAGE 2
#define SMEM_BYTES  (NSTAGE * STAGE_BYTES)

template<int K_TOTAL, bool FINAL>
__global__ __launch_bounds__(128, 4) void fused_layer_kernel(
    const __half* __restrict__ A,
    const __half* __restrict__ W,
    const float* __restrict__ Cb,
    __half* __restrict__ Oact,
    float* __restrict__ Osum)
{
    extern __shared__ char smem_raw[];
    char* tb = smem_raw;
    const uint32_t sb = smem_u32(tb);

    const int tid  = threadIdx.x;
    const int wid  = tid >> 5;     // 0..3 = warp_m
    const int lane = tid & 31;
    const int m0 = blockIdx.y * 128;
    const int n0 = blockIdx.x * 64;
    const int set = m0 >> 10;

    float acc[2][8][4];
#pragma unroll
    for (int a = 0; a < 2; a++)
#pragma unroll
        for (int b = 0; b < 8; b++)
#pragma unroll
            for (int c = 0; c < 4; c++) acc[a][b][c] = 0.f;

    const int NCHUNK = K_TOTAL / 64;

    // A: 128 rows x 128B = 1024 x 16B units (8/thread); W: 64 rows = 512 units (4/thread)
    auto issue_chunk = [&](int ch, int st) {
        const uint32_t sbase = sb + st * STAGE_BYTES;
#pragma unroll
        for (int i = 0; i < 8; i++) {
            int u = i * 128 + tid;
            int row = u >> 3, c16 = u & 7;
            uint32_t doff = SW128(row * 128 + c16 * 16);
            cpa16(sbase + A_PL + doff, A + (size_t)(m0 + row) * K_TOTAL + ch * 64 + c16 * 8);
        }
#pragma unroll
        for (int i = 0; i < 4; i++) {
            int u = i * 128 + tid;
            int row = u >> 3, c16 = u & 7;
            uint32_t doff = SW128(row * 128 + c16 * 16);
            cpa16(sbase + W_PL + doff, W + (size_t)(n0 + row) * K_TOTAL + ch * 64 + c16 * 8);
        }
        cpa_commit();
    };

    issue_chunk(0, 0);

    const int r16 = lane & 15;
    const int kb  = (lane >> 4) * 16;

    for (int ch = 0; ch < NCHUNK; ch++) {
        cpa_wait<0>();          // chunk ch's data is in SMEM
        __syncthreads();        // all warps done reading the other stage
        if (ch + 1 < NCHUNK) issue_chunk(ch + 1, (ch + 1) & 1);  // overlaps compute below

        const uint32_t sbase = sb + (ch & 1) * STAGE_BYTES;
#pragma unroll
        for (int kk = 0; kk < 4; kk++) {
            const uint32_t colb = (uint32_t)(kk * 32 + kb);
            uint32_t ah[2][4];
#pragma unroll
            for (int mt = 0; mt < 2; mt++) {
                uint32_t off = SW128((wid * 32 + mt * 16 + r16) * 128 + colb);
                ldsm_x4(ah[mt], sbase + A_PL + off);
            }
#pragma unroll
            for (int p = 0; p < 4; p++) {
                uint32_t offB = SW128((p * 16 + r16) * 128 + colb);
                uint32_t bh[4];
                ldsm_x4(bh, sbase + W_PL + offB);
#pragma unroll
                for (int mt = 0; mt < 2; mt++) {
                    mma_fp16(acc[mt][2 * p],     ah[mt], bh[0], bh[2]);
                    mma_fp16(acc[mt][2 * p + 1], ah[mt], bh[1], bh[3]);
                }
            }
        }
        __syncthreads();        // reads of this stage done before next overwrite
    }

    // ---- epilogue ----
    float* cbs = (float*)tb;    // stage reads all done (barrier above)
    if (tid < 64) cbs[tid] = Cb[set * 256 + n0 + tid];
    __syncthreads();

    const int lq = lane >> 2;
    const int lr = lane & 3;

    float colsum[8][2];
#pragma unroll
    for (int nt = 0; nt < 8; nt++) { colsum[nt][0] = 0.f; colsum[nt][1] = 0.f; }

#pragma unroll
    for (int mt = 0; mt < 2; mt++) {
        const int rbase = m0 + wid * 32 + mt * 16 + lq;
#pragma unroll
        for (int nt = 0; nt < 8; nt++) {
            const int lc = nt * 8 + 2 * lr;          // local col in [0,64)
            float v0 = tanh_fast(acc[mt][nt][0] + cbs[lc]);
            float v1 = tanh_fast(acc[mt][nt][1] + cbs[lc + 1]);
            float v2 = tanh_fast(acc[mt][nt][2] + cbs[lc]);
            float v3 = tanh_fast(acc[mt][nt][3] + cbs[lc + 1]);
            colsum[nt][0] += v0 + v2;
            colsum[nt][1] += v1 + v3;
            if (!FINAL) {
                *(uint32_t*)(Oact + (size_t)rbase * 256 + n0 + lc)       = pack2h(v0, v1);
                *(uint32_t*)(Oact + (size_t)(rbase + 8) * 256 + n0 + lc) = pack2h(v2, v3);
            }
        }
    }
#pragma unroll
    for (int nt = 0; nt < 8; nt++) {
#pragma unroll
        for (int h = 0; h < 2; h++) {
            float s = colsum[nt][h];
            s += __shfl_xor_sync(0xffffffffu, s, 4);
            s += __shfl_xor_sync(0xffffffffu, s, 8);
            s += __shfl_xor_sync(0xffffffffu, s, 16);
            if (lq == 0) {
                int gc = n0 + nt * 8 + 2 * lr + h;
                atomicAdd(Osum + set * 256 + gc, FINAL ? s * (1.0f / S_LEN) : s);
            }
        }
    }
}

// ---------------------------------------------------------------------------
extern "C" void kernel_launch(void* const* d_in, const int* in_sizes, int n_in,
                              void* d_out, int out_size) {
    const float* x  = (const float*)d_in[0];
    const float* W0 = (const float*)d_in[1];
    const float* b0 = (const float*)d_in[2];
    const float* W1 = (const float*)d_in[3];
    const float* b1 = (const float*)d_in[4];
    const float* W2 = (const float*)d_in[5];
    const float* b2 = (const float*)d_in[6];
    float* out = (float*)d_out;

    __half *act1, *act2, *w0, *w1, *w2;
    float *msum, *cb;
    cudaGetSymbolAddress((void**)&act1, g_act1);
    cudaGetSymbolAddress((void**)&act2, g_act2);
    cudaGetSymbolAddress((void**)&w0, g_w0);
    cudaGetSymbolAddress((void**)&w1, g_w1);
    cudaGetSymbolAddress((void**)&w2, g_w2);
    cudaGetSymbolAddress((void**)&msum, g_msum);
    cudaGetSymbolAddress((void**)&cb,   g_cb);

    cudaFuncSetAttribute(fused_layer_kernel<128, false>,
                         cudaFuncAttributeMaxDynamicSharedMemorySize, SMEM_BYTES);
    cudaFuncSetAttribute(fused_layer_kernel<256, false>,
                         cudaFuncAttributeMaxDynamicSharedMemorySize, SMEM_BYTES);
    cudaFuncSetAttribute(fused_layer_kernel<256, true>,
                         cudaFuncAttributeMaxDynamicSharedMemorySize, SMEM_BYTES);

    dim3 gg(4, M_ROWS / 128);   // x = n-block (64 cols each); adjacent -> L2 reuse of A

    // prep: all weights in one launch; zero out early; x plane + mean fused.
    prep_w_all_kernel<<<3 * H_DIM, 256>>>(W0, W1, W2, w0, w1, w2);
    zero_kernel<<<B_SETS, 256>>>(out, B_SETS * H_DIM);
    prep_x_mean_kernel<<<dim3(B_SETS, 8), 128>>>(x, act2, msum);

    // Layer 0
    cbias_kernel<<<B_SETS, H_DIM>>>(msum, W0, b0, cb, msum, 128, 256, 128);
    fused_layer_kernel<128, false><<<gg, 128, SMEM_BYTES>>>(
        act2, w0, cb, act1, msum);

    // Layer 1
    cbias_kernel<<<B_SETS, H_DIM>>>(msum, W1, b1, cb, msum, 256, 512, 256);
    fused_layer_kernel<256, false><<<gg, 128, SMEM_BYTES>>>(
        act1, w1, cb, act2, msum);

    // Layer 2 (final)
    cbias_kernel<<<B_SETS, H_DIM>>>(msum, W2, b2, cb, msum, 256, 512, 256);
    fused_layer_kernel<256, true><<<gg, 128, SMEM_BYTES>>>(
        act2, w2, cb, nullptr, out);
}

// round 17
// speedup vs baseline: 1.5104x; 1.5104x over previous
#include <cuda_runtime.h>
#include <cuda_fp16.h>
#include <cstdint>

#define B_SETS 256
#define S_LEN  1024
#define H_DIM  256
#define M_ROWS (B_SETS * S_LEN)

// ---------------------------------------------------------------------------
// Scratch (__device__ globals; allocation-free rule)
// ---------------------------------------------------------------------------
__device__ __half g_act1[(size_t)M_ROWS * H_DIM];  // 128 MB
__device__ __half g_act2[(size_t)M_ROWS * H_DIM];  // 128 MB (x plane for L0)
__device__ __half g_w0[H_DIM * 128];
__device__ __half g_w1[H_DIM * H_DIM];
__device__ __half g_w2[H_DIM * H_DIM];
__device__ float g_mpart[B_SETS * 8 * H_DIM];  // per-(set, m-block) column sums
__device__ float g_cb[B_SETS * H_DIM];         // per-set bias c[b,h]

// ---------------------------------------------------------------------------
// helpers
// ---------------------------------------------------------------------------
__device__ __forceinline__ uint32_t smem_u32(const void* p) {
    uint32_t a;
    asm("{ .reg .u64 t; cvta.to.shared.u64 t, %1; cvt.u32.u64 %0, t; }" : "=r"(a) : "l"(p));
    return a;
}
#define SW128(o) ((uint32_t)(o) ^ ((((uint32_t)(o)) >> 3) & 0x70u))

__device__ __forceinline__ void ldsm_x4(uint32_t* r, uint32_t addr) {
    asm volatile("ldmatrix.sync.aligned.m8n8.x4.shared.b16 {%0,%1,%2,%3}, [%4];"
                 : "=r"(r[0]), "=r"(r[1]), "=r"(r[2]), "=r"(r[3]) : "r"(addr));
}
__device__ __forceinline__ void mma_fp16(float* d, const uint32_t* a, uint32_t b0, uint32_t b1) {
    asm volatile(
        "mma.sync.aligned.m16n8k16.row.col.f32.f16.f16.f32 "
        "{%0,%1,%2,%3},{%4,%5,%6,%7},{%8,%9},{%0,%1,%2,%3};"
        : "+f"(d[0]), "+f"(d[1]), "+f"(d[2]), "+f"(d[3])
        : "r"(a[0]), "r"(a[1]), "r"(a[2]), "r"(a[3]), "r"(b0), "r"(b1));
}
__device__ __forceinline__ float tanh_fast(float x) {
    float r;
    asm("tanh.approx.f32 %0, %1;" : "=f"(r) : "f"(x));
    return r;
}
__device__ __forceinline__ uint32_t pack2h(float a, float b) {
    __half2 t = __floats2half2_rn(a, b);
    return *reinterpret_cast<uint32_t*>(&t);
}
__device__ __forceinline__ void cpa16(uint32_t dst, const void* src) {
    asm volatile("cp.async.cg.shared.global [%0], [%1], 16;" :: "r"(dst), "l"(src));
}
__device__ __forceinline__ void cpa_commit() {
    asm volatile("cp.async.commit_group;");
}
template<int N>
__device__ __forceinline__ void cpa_wait() {
    asm volatile("cp.async.wait_group %0;" :: "n"(N));
}

// ---------------------------------------------------------------------------
// small kernels
// ---------------------------------------------------------------------------
__global__ void prep_w_all_kernel(const float* __restrict__ W0,
                                  const float* __restrict__ W1,
                                  const float* __restrict__ W2,
                                  __half* __restrict__ w0h,
                                  __half* __restrict__ w1h,
                                  __half* __restrict__ w2h) {
    int blk = blockIdx.x;
    const float* W; __half* O; int ldw, K, n;
    if (blk < 256)      { W = W0; O = w0h; ldw = 256; K = 128; n = blk; }
    else if (blk < 512) { W = W1; O = w1h; ldw = 512; K = 256; n = blk - 256; }
    else                { W = W2; O = w2h; ldw = 512; K = 256; n = blk - 512; }
    for (int k = threadIdx.x; k < K; k += blockDim.x)
        O[n * K + k] = __float2half_rn(W[(size_t)n * ldw + k]);
}

// x fp32 -> fp16 plane AND per-(set, m-block) column-sum partials (no atomics).
// grid (B_SETS, 8), block 128.
__global__ void prep_x_mean_kernel(const float* __restrict__ x,
                                   __half* __restrict__ hi,
                                   float* __restrict__ mpart) {
    int b = blockIdx.x, cz = blockIdx.y, t = threadIdx.x;
    size_t base = (size_t)b * S_LEN * 128 + (size_t)cz * 128 * 128;
    const float* p = x + base + t;
    __half* o = hi + base + t;
    float s = 0.f;
#pragma unroll 8
    for (int i = 0; i < 128; i++) {
        float f = p[(size_t)i * 128];
        s += f;
        o[(size_t)i * 128] = __float2half_rn(f);
    }
    mpart[(b * 8 + cz) * H_DIM + t] = s;   // cols [0,128); cbias(K=128) reads only these
}

// c[b,h] = bias[h] + (1/S) * sum_k mean[b,k] * W[h, koff+k]
// mean from 8 partials. One warp per h: grid (B_SETS, 32), block 256 (8 warps).
__global__ void cbias_kernel(const float* __restrict__ mpart, const float* __restrict__ W,
                             const float* __restrict__ bias, float* __restrict__ c,
                             int K, int ldw, int koff) {
    __shared__ float ms[H_DIM];
    int b = blockIdx.x, tid = threadIdx.x, wid = tid >> 5, lane = tid & 31;
    if (tid < K) {
        float s = 0.f;
#pragma unroll
        for (int i = 0; i < 8; i++) s += mpart[(b * 8 + i) * H_DIM + tid];
        ms[tid] = s * (1.0f / S_LEN);
    }
    __syncthreads();
    int h = blockIdx.y * 8 + wid;
    const float* wr = W + (size_t)h * ldw + koff;
    float s = 0.f;
#pragma unroll
    for (int k0 = 0; k0 < 256 && k0 < K; k0 += 128) {
        float4 w4 = *(const float4*)(wr + k0 + lane * 4);
        const float* m4 = ms + k0 + lane * 4;
        s += m4[0] * w4.x + m4[1] * w4.y + m4[2] * w4.z + m4[3] * w4.w;
    }
    s += __shfl_xor_sync(0xffffffffu, s, 16);
    s += __shfl_xor_sync(0xffffffffu, s, 8);
    s += __shfl_xor_sync(0xffffffffu, s, 4);
    s += __shfl_xor_sync(0xffffffffu, s, 2);
    s += __shfl_xor_sync(0xffffffffu, s, 1);
    if (lane == 0) c[b * H_DIM + h] = s + bias[h];
}

// out[b,h] = (1/S) * sum_i mpart[b][i][h].  grid B_SETS, block 256.
__global__ void final_reduce_kernel(const float* __restrict__ mpart, float* __restrict__ out) {
    int b = blockIdx.x, h = threadIdx.x;
    float s = 0.f;
#pragma unroll
    for (int i = 0; i < 8; i++) s += mpart[(b * 8 + i) * H_DIM + h];
    out[b * H_DIM + h] = s * (1.0f / S_LEN);
}

// ---------------------------------------------------------------------------
// Fused layer (fp16 HMMA, cp.async 3-stage pipeline, single barrier/chunk):
// CTA: Out[128 x 128] = tanh(A[128xK] W[128xK]^T + cbias)
// K chunk 64 (128B rows, SW128). 8 warps: 4 in M x 2 in N.
// Grid (2, M/128): n-pairs adjacent -> L2 reuse of A.
// Epilogue: SMEM cross-warp reduce -> partial write (atomic-free).
// ---------------------------------------------------------------------------
#define A_PL 0
#define W_PL 16384
#define STAGE_BYTES 32768
#define NSTAGE 3
#define SMEM_BYTES  (NSTAGE * STAGE_BYTES)

template<int K_TOTAL, bool FINAL>
__global__ __launch_bounds__(256, 2) void fused_layer_kernel(
    const __half* __restrict__ A,
    const __half* __restrict__ W,
    const float* __restrict__ Cb,
    __half* __restrict__ Oact,
    float* __restrict__ Mpart)
{
    extern __shared__ char smem_raw[];
    char* tb = smem_raw;
    const uint32_t sb = smem_u32(tb);

    const int tid  = threadIdx.x;
    const int wid  = tid >> 5;
    const int lane = tid & 31;
    const int warp_m = wid & 3;
    const int warp_n = wid >> 2;
    const int m0 = blockIdx.y * 128;   // y is the M dimension
    const int n0 = blockIdx.x * 128;   // x is the (2-wide) N dimension
    const int set  = m0 >> 10;
    const int mblk = blockIdx.y & 7;

    float acc[2][8][4];
#pragma unroll
    for (int a = 0; a < 2; a++)
#pragma unroll
        for (int b = 0; b < 8; b++)
#pragma unroll
            for (int c = 0; c < 4; c++) acc[a][b][c] = 0.f;

    const int NCHUNK = K_TOTAL / 64;

    auto issue_chunk = [&](int ch, int st) {
        const uint32_t sbase = sb + st * STAGE_BYTES;
#pragma unroll
        for (int i = 0; i < 4; i++) {
            int u = i * 256 + tid;
            int row = u >> 3, c16 = u & 7;
            uint32_t doff = SW128(row * 128 + c16 * 16);
            size_t asrc = (size_t)(m0 + row) * K_TOTAL + ch * 64 + c16 * 8;
            size_t wsrc = (size_t)(n0 + row) * K_TOTAL + ch * 64 + c16 * 8;
            cpa16(sbase + A_PL + doff, A + asrc);
            cpa16(sbase + W_PL + doff, W + wsrc);
        }
        cpa_commit();
    };

    issue_chunk(0, 0);
    if (NCHUNK > 1) issue_chunk(1, 1);

    const int r16 = lane & 15;
    const int kb  = (lane >> 4) * 16;

    for (int ch = 0; ch < NCHUNK; ch++) {
        const int st = ch % NSTAGE;
        if (ch + 1 < NCHUNK) cpa_wait<1>(); else cpa_wait<0>();
        __syncthreads();
        if (ch + 2 < NCHUNK) issue_chunk(ch + 2, (ch + 2) % NSTAGE);

        const uint32_t sbase = sb + st * STAGE_BYTES;
#pragma unroll
        for (int kk = 0; kk < 4; kk++) {
            const uint32_t colb = (uint32_t)(kk * 32 + kb);
            uint32_t ah[2][4];
#pragma unroll
            for (int mt = 0; mt < 2; mt++) {
                uint32_t off = SW128((warp_m * 32 + mt * 16 + r16) * 128 + colb);
                ldsm_x4(ah[mt], sbase + A_PL + off);
            }
#pragma unroll
            for (int p = 0; p < 4; p++) {
                uint32_t offB = SW128((warp_n * 64 + p * 16 + r16) * 128 + colb);
                uint32_t bh[4];
                ldsm_x4(bh, sbase + W_PL + offB);
#pragma unroll
                for (int mt = 0; mt < 2; mt++) {
                    mma_fp16(acc[mt][2 * p],     ah[mt], bh[0], bh[2]);
                    mma_fp16(acc[mt][2 * p + 1], ah[mt], bh[1], bh[3]);
                }
            }
        }
    }
    __syncthreads();   // all stage reads done before reusing tb below

    // ---- epilogue ----
    float* cbs = (float*)tb;             // [128] bias for this n-range
    float* red = (float*)(tb + 1024);    // [4][128] cross-warp colsum staging
    if (tid < 128) cbs[tid] = Cb[set * 256 + n0 + tid];
    __syncthreads();

    const int lq = lane >> 2;
    const int lr = lane & 3;

    float colsum[8][2];
#pragma unroll
    for (int nt = 0; nt < 8; nt++) { colsum[nt][0] = 0.f; colsum[nt][1] = 0.f; }

#pragma unroll
    for (int mt = 0; mt < 2; mt++) {
        const int rbase = m0 + warp_m * 32 + mt * 16 + lq;
#pragma unroll
        for (int nt = 0; nt < 8; nt++) {
            const int lc = warp_n * 64 + nt * 8 + 2 * lr;
            float v0 = tanh_fast(acc[mt][nt][0] + cbs[lc]);
            float v1 = tanh_fast(acc[mt][nt][1] + cbs[lc + 1]);
            float v2 = tanh_fast(acc[mt][nt][2] + cbs[lc]);
            float v3 = tanh_fast(acc[mt][nt][3] + cbs[lc + 1]);
            colsum[nt][0] += v0 + v2;
            colsum[nt][1] += v1 + v3;
            if (!FINAL) {
                *(uint32_t*)(Oact + (size_t)rbase * 256 + n0 + lc)       = pack2h(v0, v1);
                *(uint32_t*)(Oact + (size_t)(rbase + 8) * 256 + n0 + lc) = pack2h(v2, v3);
            }
        }
    }
    // warp-level reduce over row groups, then stage per-warp col sums in smem
#pragma unroll
    for (int nt = 0; nt < 8; nt++) {
#pragma unroll
        for (int h = 0; h < 2; h++) {
            float s = colsum[nt][h];
            s += __shfl_xor_sync(0xffffffffu, s, 4);
            s += __shfl_xor_sync(0xffffffffu, s, 8);
            s += __shfl_xor_sync(0xffffffffu, s, 16);
            if (lq == 0)
                red[warp_m * 128 + warp_n * 64 + nt * 8 + 2 * lr + h] = s;
        }
    }
    __syncthreads();
    if (tid < 128) {
        float s = red[tid] + red[128 + tid] + red[256 + tid] + red[384 + tid];
        Mpart[(set * 8 + mblk) * H_DIM + n0 + tid] = s;
    }
}

// ---------------------------------------------------------------------------
extern "C" void kernel_launch(void* const* d_in, const int* in_sizes, int n_in,
                              void* d_out, int out_size) {
    const float* x  = (const float*)d_in[0];
    const float* W0 = (const float*)d_in[1];
    const float* b0 = (const float*)d_in[2];
    const float* W1 = (const float*)d_in[3];
    const float* b1 = (const float*)d_in[4];
    const float* W2 = (const float*)d_in[5];
    const float* b2 = (const float*)d_in[6];
    float* out = (float*)d_out;

    __half *act1, *act2, *w0, *w1, *w2;
    float *mpart, *cb;
    cudaGetSymbolAddress((void**)&act1, g_act1);
    cudaGetSymbolAddress((void**)&act2, g_act2);
    cudaGetSymbolAddress((void**)&w0, g_w0);
    cudaGetSymbolAddress((void**)&w1, g_w1);
    cudaGetSymbolAddress((void**)&w2, g_w2);
    cudaGetSymbolAddress((void**)&mpart, g_mpart);
    cudaGetSymbolAddress((void**)&cb,    g_cb);

    cudaFuncSetAttribute(fused_layer_kernel<128, false>,
                         cudaFuncAttributeMaxDynamicSharedMemorySize, SMEM_BYTES);
    cudaFuncSetAttribute(fused_layer_kernel<256, false>,
                         cudaFuncAttributeMaxDynamicSharedMemorySize, SMEM_BYTES);
    cudaFuncSetAttribute(fused_layer_kernel<256, true>,
                         cudaFuncAttributeMaxDynamicSharedMemorySize, SMEM_BYTES);

    dim3 gg(2, M_ROWS / 128);          // x = n-block (pairs adjacent -> L2 reuse of A)
    dim3 gcb(B_SETS, 32);              // cbias: one warp per output h

    // prep: all weights in one launch; x plane + mean partials fused.
    prep_w_all_kernel<<<3 * H_DIM, 256>>>(W0, W1, W2, w0, w1, w2);
    prep_x_mean_kernel<<<dim3(B_SETS, 8), 128>>>(x, act2, mpart);

    // Layer 0
    cbias_kernel<<<gcb, 256>>>(mpart, W0, b0, cb, 128, 256, 128);
    fused_layer_kernel<128, false><<<gg, 256, SMEM_BYTES>>>(
        act2, w0, cb, act1, mpart);

    // Layer 1
    cbias_kernel<<<gcb, 256>>>(mpart, W1, b1, cb, 256, 512, 256);
    fused_layer_kernel<256, false><<<gg, 256, SMEM_BYTES>>>(
        act1, w1, cb, act2, mpart);

    // Layer 2 (final): partials -> final_reduce -> out
    cbias_kernel<<<gcb, 256>>>(mpart, W2, b2, cb, 256, 512, 256);
    fused_layer_kernel<256, true><<<gg, 256, SMEM_BYTES>>>(
        act2, w2, cb, nullptr, mpart);
    final_reduce_kernel<<<B_SETS, 256>>>(mpart, out);
}